// round 11
// baseline (speedup 1.0000x reference)
#include <cuda_runtime.h>
#include <cuda_bf16.h>
#include <math.h>
#include <stdint.h>

#define DIM   512
#define N_ELEM (DIM*DIM)       // 262144
#define KFLAT 1024             // DT*2
#define NB    128              // persistent CTAs (all co-resident)
#define NTH   512
#define NPT   4                // elements per thread: 262144/(128*512)

// dynamic smem layout
#define CHUNK_B   8192         // 64 rows x 128 bytes
#define BP_BYTES  (16 * CHUNK_B)   // persistent B: 16 chunks = 128KB
#define NSTAGE    4
#define ASTG_OFF  BP_BYTES
#define SMEM_DYN  (BP_BYTES + NSTAGE * CHUNK_B)   // 160KB

// ---------------- device state ----------------
__device__ float g_A[N_ELEM];                // y
__device__ float g_K[7][2][N_ELEM];          // k1..k7, split-K partials
__device__ float g_ynew[N_ELEM];
__device__ __align__(16) __nv_bfloat16 g_bhi[N_ELEM*2];  // basis hi [row][j*2+k]
__device__ __align__(16) __nv_bfloat16 g_blo[N_ELEM*2];  // basis lo
__device__ __align__(16) __nv_bfloat16 g_Chi[DIM*KFLAT]; // C hi
__device__ __align__(16) __nv_bfloat16 g_Clo[DIM*KFLAT]; // C lo
__device__ float g_red[2*NB];
__device__ int   g_bar_cnt;
__device__ int   g_bar_epoch;

// stage coefficient tables (Dormand-Prince)
__constant__ float STG_C[8][6] = {
  {0.f,0.f,0.f,0.f,0.f,0.f},
  {1.f,0.f,0.f,0.f,0.f,0.f},
  {0.2f,0.f,0.f,0.f,0.f,0.f},
  {3.f/40.f, 9.f/40.f, 0.f,0.f,0.f,0.f},
  {44.f/45.f, -56.f/15.f, 32.f/9.f, 0.f,0.f,0.f},
  {19372.f/6561.f, -25360.f/2187.f, 64448.f/6561.f, -212.f/729.f,0.f,0.f},
  {9017.f/3168.f, -355.f/33.f, 46732.f/5247.f, 49.f/176.f, -5103.f/18656.f, 0.f},
  {35.f/384.f, 0.f, 500.f/1113.f, 125.f/192.f, -2187.f/6784.f, 11.f/84.f},
};
__constant__ float STG_T[8] = {0.f, 1.f, 0.2f, 0.3f, 0.8f, 8.f/9.f, 1.f, 1.f};
__constant__ float ERR_C[6] = { 71.f/57600.f, -71.f/16695.f, 71.f/1920.f,
                                -17253.f/339200.f, 22.f/525.f, -1.f/40.f };
__constant__ int ERR_IDX[6] = {0, 2, 3, 4, 5, 6};

#define SWZ128(o) ((o) ^ (((o) >> 3) & 0x70))

__device__ __forceinline__ uint32_t smem_u32(const void* p) {
  uint32_t a;
  asm("{ .reg .u64 t; cvta.to.shared.u64 t, %1; cvt.u32.u64 %0, t; }" : "=r"(a) : "l"(p));
  return a;
}

#define CP_ASYNC16(sm, gp) \
  asm volatile("cp.async.cg.shared.global [%0], [%1], 16;" :: "r"(sm), "l"(gp) : "memory")
#define CP_COMMIT()  asm volatile("cp.async.commit_group;" ::: "memory")
#define CP_WAIT2()   asm volatile("cp.async.wait_group 2;" ::: "memory")
#define CP_WAIT0()   asm volatile("cp.async.wait_group 0;" ::: "memory")

// ---------------- grid barrier ----------------
__device__ __forceinline__ void gridbar(int* s_epoch) {
  __syncthreads();
  if (threadIdx.x == 0) {
    int e = ++(*s_epoch);
    __threadfence();
    if (atomicAdd(&g_bar_cnt, 1) == NB - 1) {
      g_bar_cnt = 0;
      __threadfence();
      atomicExch(&g_bar_epoch, e);
    } else {
      while (*((volatile int*)&g_bar_epoch) < e) { }
    }
    __threadfence();
  }
  __syncthreads();
}

// ---------------- elementwise stage ----------------
__device__ __forceinline__ void stage_dev(int sid, int nK, int writeYnew,
                                          float hs, float t, int id) {
  float ts = t + STG_T[sid] * hs;
  int base = id * (NTH * NPT) + threadIdx.x;
  #pragma unroll
  for (int r = 0; r < NPT; r++) {
    int i = base + r * NTH;
    float y = __ldcg(&g_A[i]);
    float yt = y;
    if (nK > 0) {
      float acc = 0.f;
      for (int j = 0; j < nK; j++)
        acc += STG_C[sid][j] * (__ldcg(&g_K[j][0][i]) + __ldcg(&g_K[j][1][i]));
      yt = y + hs * acc;
    }
    if (writeYnew) g_ynew[i] = yt;
    float ph = yt + ts;
    float s, c;
    sincosf(ph, &s, &c);
    __nv_bfloat16 sh = __float2bfloat16(s);
    __nv_bfloat16 ch = __float2bfloat16(c);
    float sr = s - __bfloat162float(sh);
    float cr = c - __bfloat162float(ch);
    ((__nv_bfloat162*)g_bhi)[i] = __nv_bfloat162(sh, ch);
    ((__nv_bfloat162*)g_blo)[i] = __nv_bfloat162(__float2bfloat16(sr), __float2bfloat16(cr));
  }
}

// ---------------- bf16 mma GEMM NT (B resident in smem, cp.async A pipe) ----
__device__ __forceinline__ void mma_bf16(float* c, uint32_t a0, uint32_t a1,
                                         uint32_t a2, uint32_t a3,
                                         uint32_t b0, uint32_t b1) {
  asm volatile("mma.sync.aligned.m16n8k16.row.col.f32.bf16.bf16.f32 "
               "{%0,%1,%2,%3}, {%4,%5,%6,%7}, {%8,%9}, {%0,%1,%2,%3};"
               : "+f"(c[0]), "+f"(c[1]), "+f"(c[2]), "+f"(c[3])
               : "r"(a0), "r"(a1), "r"(a2), "r"(a3), "r"(b0), "r"(b1));
}

// chunk tk (0..23): seg=tk>>3: 0=Ah*Bh, 1=Ah*Bl, 2=Al*Bh
__device__ __forceinline__ const __nv_bfloat16* srcA_of(int tk) {
  return (tk >> 3) == 2 ? g_blo : g_bhi;
}
__device__ __forceinline__ int cbB_of(int tk) {          // persistent B chunk idx
  return ((tk >> 3) == 1) ? 8 + (tk & 7) : (tk & 7);
}

__device__ void gemm_nt_mma(int dstId, int row0, int col0, int kbase, int bz,
                            char* dynsm) {
  float* D = &g_K[dstId][bz][0];
  int tid = threadIdx.x, wid = tid >> 5, lane = tid & 31;
  int wr = wid >> 2, wc = wid & 3;             // 4x4 warps, tile 16x16

  // A global->smem: 512 x 16B per chunk, 1 per thread
  int lrowA = tid >> 3, lchA = tid & 7;
  uint32_t soA = SWZ128((uint32_t)(lrowA * 128 + lchA * 16));
  uint32_t AsmBase = smem_u32(dynsm + ASTG_OFF);
  uint32_t Bsm = smem_u32(dynsm);

  // ldmatrix lane roles
  int g = lane >> 3, r = lane & 7;
  int a_m = ((g & 1) ? 8 : 0) + r;
  int a_k = (g >> 1) * 8;
  int b_n = ((g >> 1) ? 8 : 0) + r;
  int b_k = (g & 1) * 8;

  float acc[2][4] = {};

  // prologue: issue chunks 0..2
  #pragma unroll
  for (int p = 0; p < 3; p++) {
    const __nv_bfloat16* As = srcA_of(p);
    int koff = kbase + (p & 7) * 64;
    CP_ASYNC16(AsmBase + p * CHUNK_B + soA,
               &As[(size_t)(row0 + lrowA) * KFLAT + koff + lchA * 8]);
    CP_COMMIT();
  }

  for (int tk = 0; tk < 24; tk++) {
    CP_WAIT2();
    __syncthreads();
    if (tk + 3 < 24) {
      int nt = tk + 3;
      const __nv_bfloat16* As = srcA_of(nt);
      int koff = kbase + (nt & 7) * 64;
      CP_ASYNC16(AsmBase + (nt & 3) * CHUNK_B + soA,
                 &As[(size_t)(row0 + lrowA) * KFLAT + koff + lchA * 8]);
    }
    CP_COMMIT();   // every thread, every iter: uniform group count

    uint32_t Ab = AsmBase + (tk & 3) * CHUNK_B;
    uint32_t Bb = Bsm + cbB_of(tk) * CHUNK_B;
    #pragma unroll
    for (int s = 0; s < 4; s++) {
      uint32_t a0, a1, a2, a3, b0, b1, b2, b3;
      uint32_t addrA = Ab + SWZ128((uint32_t)((wr * 16 + a_m) * 128 + (s * 16 + a_k) * 2));
      asm volatile("ldmatrix.sync.aligned.m8n8.x4.shared.b16 {%0,%1,%2,%3}, [%4];"
                   : "=r"(a0), "=r"(a1), "=r"(a2), "=r"(a3) : "r"(addrA));
      uint32_t addrB = Bb + SWZ128((uint32_t)((wc * 16 + b_n) * 128 + (s * 16 + b_k) * 2));
      asm volatile("ldmatrix.sync.aligned.m8n8.x4.shared.b16 {%0,%1,%2,%3}, [%4];"
                   : "=r"(b0), "=r"(b1), "=r"(b2), "=r"(b3) : "r"(addrB));
      mma_bf16(acc[0], a0, a1, a2, a3, b0, b1);
      mma_bf16(acc[1], a0, a1, a2, a3, b2, b3);
    }
  }
  CP_WAIT0();

  // epilogue
  int mrow = row0 + wr * 16 + (lane >> 2);
  int ncol = col0 + wc * 16 + (lane & 3) * 2;
  #pragma unroll
  for (int nf = 0; nf < 2; nf++) {
    float2 lo = {acc[nf][0], acc[nf][1]};
    float2 hi = {acc[nf][2], acc[nf][3]};
    *(float2*)&D[(size_t)mrow       * DIM + ncol + nf * 8] = lo;
    *(float2*)&D[(size_t)(mrow + 8) * DIM + ncol + nf * 8] = hi;
  }
  __syncthreads();
}

// ---------------- block reduce (512 threads) ----------------
__device__ __forceinline__ float blockReduce(float v, float* sh) {
  int tid = threadIdx.x;
  sh[tid] = v; __syncthreads();
  for (int s = 256; s > 0; s >>= 1) {
    if (tid < s) sh[tid] += sh[tid + s];
    __syncthreads();
  }
  float r = sh[0];
  __syncthreads();
  return r;
}

__device__ __forceinline__ float gridSum(int ofs) {
  float S = 0.f;
  for (int b = 0; b < NB; b++) S += __ldcg(&g_red[ofs + b]);
  return S;
}

// ---------------- persistent ODE kernel ----------------
__global__ __launch_bounds__(NTH) void k_ode() {
  extern __shared__ char dynsm[];
  __shared__ float sred[NTH];
  __shared__ int   s_epoch;
  int tid = threadIdx.x, id = blockIdx.x;
  int bx = id & 7, by = (id >> 3) & 7, bz = id >> 6;
  int row0 = by * 64, col0 = bx * 64, kbase = bz * 512;
  if (tid == 0) s_epoch = 0;

  // ---- load persistent B (C hi/lo tiles for this CTA) into smem once ----
  for (int i = tid; i < 16 * 512; i += NTH) {
    int cb = i >> 9, c = i & 511;
    int lrow = c >> 3, lch = c & 7;
    const __nv_bfloat16* src = (cb < 8) ? g_Chi : g_Clo;
    int koff = kbase + (cb & 7) * 64;
    uint4 v = *(const uint4*)&src[(size_t)(col0 + lrow) * KFLAT + koff + lch * 8];
    *(uint4*)(dynsm + cb * CHUNK_B + SWZ128((uint32_t)(lrow * 128 + lch * 16))) = v;
  }
  __syncthreads();

  int base = id * (NTH * NPT) + tid;

  // ---- f0 = f(0, A0) ----
  stage_dev(0, 0, 0, 0.f, 0.f, id);
  gridbar(&s_epoch);
  gemm_nt_mma(0, row0, col0, kbase, bz, dynsm);
  gridbar(&s_epoch);

  // ---- initial step size: d0, d1 ----
  {
    float s0 = 0.f, s1 = 0.f;
    #pragma unroll
    for (int r = 0; r < NPT; r++) {
      int i = base + r * NTH;
      float y = __ldcg(&g_A[i]);
      float f = __ldcg(&g_K[0][0][i]) + __ldcg(&g_K[0][1][i]);
      float sc = 1e-6f + 1e-3f * fabsf(y);
      float a = y / sc, b = f / sc;
      s0 += a * a; s1 += b * b;
    }
    float S0 = blockReduce(s0, sred);
    float S1 = blockReduce(s1, sred);
    if (tid == 0) { g_red[id] = S0; g_red[NB + id] = S1; }
  }
  gridbar(&s_epoch);
  float S0 = gridSum(0), S1 = gridSum(NB);
  float d0 = sqrtf(S0 / (float)N_ELEM);
  float d1 = sqrtf(S1 / (float)N_ELEM);
  float h0 = (d0 < 1e-5f || d1 < 1e-5f) ? 1e-6f : 0.01f * d0 / d1;

  // ---- f1 = f(h0, y0 + h0*f0) -> g_K[1] ----
  stage_dev(1, 1, 0, h0, 0.f, id);
  gridbar(&s_epoch);
  gemm_nt_mma(1, row0, col0, kbase, bz, dynsm);
  gridbar(&s_epoch);
  {
    float s = 0.f;
    #pragma unroll
    for (int r = 0; r < NPT; r++) {
      int i = base + r * NTH;
      float y = __ldcg(&g_A[i]);
      float sc = 1e-6f + 1e-3f * fabsf(y);
      float f0 = __ldcg(&g_K[0][0][i]) + __ldcg(&g_K[0][1][i]);
      float f1 = __ldcg(&g_K[1][0][i]) + __ldcg(&g_K[1][1][i]);
      float d = (f1 - f0) / sc;
      s += d * d;
    }
    float S = blockReduce(s, sred);
    if (tid == 0) g_red[id] = S;
  }
  gridbar(&s_epoch);
  float d2 = sqrtf(gridSum(0) / (float)N_ELEM) / h0;
  float dmax = fmaxf(d1, d2);
  float h1 = (dmax <= 1e-15f) ? fmaxf(1e-6f, h0 * 1e-3f)
                              : powf(0.01f / dmax, 0.2f);
  float h = fminf(fminf(100.f * h0, h1), 1.0f);
  float t = 0.f;

  // ---- adaptive loop ----
  for (int step = 0; step < 20; step++) {
    float hs = fminf(h, 1.0f - t);

    stage_dev(2, 1, 0, hs, t, id); gridbar(&s_epoch);
    gemm_nt_mma(1, row0, col0, kbase, bz, dynsm); gridbar(&s_epoch);  // k2
    stage_dev(3, 2, 0, hs, t, id); gridbar(&s_epoch);
    gemm_nt_mma(2, row0, col0, kbase, bz, dynsm); gridbar(&s_epoch);  // k3
    stage_dev(4, 3, 0, hs, t, id); gridbar(&s_epoch);
    gemm_nt_mma(3, row0, col0, kbase, bz, dynsm); gridbar(&s_epoch);  // k4
    stage_dev(5, 4, 0, hs, t, id); gridbar(&s_epoch);
    gemm_nt_mma(4, row0, col0, kbase, bz, dynsm); gridbar(&s_epoch);  // k5
    stage_dev(6, 5, 0, hs, t, id); gridbar(&s_epoch);
    gemm_nt_mma(5, row0, col0, kbase, bz, dynsm); gridbar(&s_epoch);  // k6
    stage_dev(7, 6, 1, hs, t, id); gridbar(&s_epoch);
    gemm_nt_mma(6, row0, col0, kbase, bz, dynsm); gridbar(&s_epoch);  // ynew + k7

    {
      float s = 0.f;
      #pragma unroll
      for (int r = 0; r < NPT; r++) {
        int i = base + r * NTH;
        float e = 0.f;
        #pragma unroll
        for (int j = 0; j < 6; j++) {
          int ki = ERR_IDX[j];
          e += ERR_C[j] * (__ldcg(&g_K[ki][0][i]) + __ldcg(&g_K[ki][1][i]));
        }
        e *= hs;
        float y = __ldcg(&g_A[i]), yn = __ldcg(&g_ynew[i]);
        float sc = 1e-6f + 1e-3f * fmaxf(fabsf(y), fabsf(yn));
        float d = e / sc;
        s += d * d;
      }
      float S = blockReduce(s, sred);
      if (tid == 0) g_red[id] = S;
    }
    gridbar(&s_epoch);
    float en = sqrtf(gridSum(0) / (float)N_ELEM);

    int accept = en < 1.0f;
    float safe = fmaxf(en, 1e-10f);
    float p = 0.9f * powf(safe, -0.2f);
    float fac = accept ? fminf(10.f, p) : fmaxf(0.2f, p);
    if (accept) t = t + hs;
    h = hs * fac;

    if (accept) {
      #pragma unroll
      for (int r = 0; r < NPT; r++) {
        int i = base + r * NTH;
        g_A[i] = __ldcg(&g_ynew[i]);
        g_K[0][0][i] = __ldcg(&g_K[6][0][i]);   // FSAL
        g_K[0][1][i] = __ldcg(&g_K[6][1][i]);
      }
    }
    if (t >= 1.0f - 1e-7f) break;
  }
}

// ---------------- barrier/state init ----------------
__global__ void k_init() { g_bar_cnt = 0; g_bar_epoch = 0; }

// ---------------- C hi/lo split ----------------
__global__ __launch_bounds__(256) void k_prep_C(const float* __restrict__ C) {
  int base = blockIdx.x * 1024 + threadIdx.x;
  #pragma unroll
  for (int r = 0; r < 4; r++) {
    int i = base + r * 256;
    float v = C[i];
    __nv_bfloat16 h = __float2bfloat16(v);
    g_Chi[i] = h;
    g_Clo[i] = __float2bfloat16(v - __bfloat162float(h));
  }
}

// ---------------- GEMM NN (SIMT fp32, 64x32 tiles, grid 16x8=128 blocks) ----
__global__ __launch_bounds__(256) void k_gemm_nn(const float* __restrict__ Aext,
                                                const float* __restrict__ Bm,
                                                float* outExt, int mode) {
  const float* A = mode ? g_A : Aext;
  float* D = mode ? outExt : g_A;
  const int K = DIM;
  __shared__ float As[16][64];
  __shared__ float Bs[16][32];
  int tid = threadIdx.x;
  int tx = tid & 15, ty = tid >> 4;       // compute: ty rows(4), tx cols(2)
  int row0 = blockIdx.y * 64, col0 = blockIdx.x * 32;
  int lr = tid >> 2;                      // A-load row 0..63
  int lc = (tid & 3) * 4;                 // A-load k
  int br = tid >> 4;                      // B-load k 0..15
  int bc = (tid & 15) * 2;                // B-load col
  float acc[4][2] = {};
  for (int k0 = 0; k0 < K; k0 += 16) {
    float4 av = *(const float4*)&A[(row0 + lr) * K + k0 + lc];
    As[lc+0][lr]=av.x; As[lc+1][lr]=av.y; As[lc+2][lr]=av.z; As[lc+3][lr]=av.w;
    float2 bv = *(const float2*)&Bm[(k0 + br) * DIM + col0 + bc];
    *(float2*)&Bs[br][bc] = bv;
    __syncthreads();
    #pragma unroll
    for (int kk = 0; kk < 16; kk++) {
      float4 a = *(const float4*)&As[kk][ty*4];
      float2 b = *(const float2*)&Bs[kk][tx*2];
      float ar[4] = {a.x,a.y,a.z,a.w};
      #pragma unroll
      for (int i = 0; i < 4; i++) {
        acc[i][0] += ar[i] * b.x;
        acc[i][1] += ar[i] * b.y;
      }
    }
    __syncthreads();
  }
  #pragma unroll
  for (int i = 0; i < 4; i++) {
    float2 o = {acc[i][0], acc[i][1]};
    *(float2*)&D[(row0 + ty*4 + i) * DIM + col0 + tx*2] = o;
  }
}

// ---------------- host launcher ----------------
extern "C" void kernel_launch(void* const* d_in, const int* in_sizes, int n_in,
                              void* d_out, int out_size) {
  const float* x = (const float*)d_in[0];
  const float* P = (const float*)d_in[1];
  const float* C = (const float*)d_in[2];
  const float* F = (const float*)d_in[3];
  float* out = (float*)d_out;

  static int smem_set = 0;
  if (!smem_set) {
    cudaFuncSetAttribute(k_ode, cudaFuncAttributeMaxDynamicSharedMemorySize, SMEM_DYN);
    smem_set = 1;
  }

  dim3 gNN(16, 8);

  k_init<<<1, 1>>>();
  k_prep_C<<<512, 256>>>(C);
  k_gemm_nn<<<gNN, 256>>>(x, P, nullptr, 0);     // A0 = x @ P
  k_ode<<<NB, NTH, SMEM_DYN>>>();                // entire RK45 integration
  k_gemm_nn<<<gNN, 256>>>(nullptr, F, out, 1);   // y_hat = A_f @ F
}